// round 16
// baseline (speedup 1.0000x reference)
#include <cuda_runtime.h>
#include <cuda_bf16.h>
#include <math.h>

// ---------------------------------------------------------------------------
// RPN 3D loss, GB300 (sm_103a) — round 16: row-pair k_main (2 anchors/thread)
//
//  k_main  : grid (36*16, 8) x 128thr. Block = (na, row-pair, image); thread =
//            column, handling the SAME column in 2 adjacent rows. iw is
//            row-independent -> shared per GT; per-row y/hgt/ar computed with
//            that row's sy (bit-identical to validated R10 arithmetic).
//            GT list = union of the 2 rows' y-overlapping GTs (zero-ih rows
//            see inter=0, which cannot alter fg/bg/candidates; agt only
//            consumed for fg anchors). 4608 blocks -> multi-wave balanced.
//  k_fixup : grid 256 x 32thr — winner by ballot, signed corrections
//            (bit-identical recomputation).
//  k_final : separate tiny grid=1 launch (fusion measured worse: single-CTA
//            issue throttle).
//
// gt_valid (jnp bool) arrives as int32.
// ---------------------------------------------------------------------------

#define FEAT_H 32
#define FEAT_W 110
#define NA 36
#define NB 8
#define NG 32
#define A_TOTAL (FEAT_H * FEAT_W * NA)   // 126720
#define STRIDEF 16.0f
#define NBUCKET 64
#define NPAIR (FEAT_H / 2)               // 16 row pairs

__device__ unsigned long long g_best[NB * NG];   // (iou_bits<<32)|(~anchor)
__device__ int g_assign_buf[NB * A_TOTAL];       // agt | fg<<8 | bg<<9 (pre-force)
__device__ double g_acc2[5 * NBUCKET];           // ce, n_act, n_fg, l2, l3

__device__ __forceinline__ float smooth_l1(float x) {
    float ax = fabsf(x);
    return ax < 1.0f ? 0.5f * ax * ax : ax - 0.5f;
}

// Single shared implementation: fix-up corrections rely on bitwise-identical
// recomputation of k_main contributions.
__device__ __forceinline__ void reg_loss(
    int a, int agt, int b,
    const float* __restrict__ b2, const float* __restrict__ b3,
    const float* __restrict__ gtb, const float* __restrict__ gt3,
    const float* __restrict__ anc, const float* __restrict__ mn,
    const float* __restrict__ sd, float& l2, float& l3)
{
    int na = a % NA;
    int hw = a / NA;
    int wc = hw % FEAT_W;
    int hr = hw / FEAT_W;
    const float* an = anc + na * 9;
    float sx = wc * STRIDEF, sy = hr * STRIDEF;
    float x1 = sx + __ldg(an + 0), y1 = sy + __ldg(an + 1);
    float x2 = sx + __ldg(an + 2), y2 = sy + __ldg(an + 3);
    float w  = x2 - x1 + 1.0f, h = y2 - y1 + 1.0f;
    float cx = x1 + 0.5f * w,  cy = y1 + 0.5f * h;

    const float* gb = gtb + (b * NG + agt) * 4;
    const float* g3 = gt3 + (b * NG + agt) * 7;
    float gx1 = __ldg(gb + 0), gy1 = __ldg(gb + 1);
    float gx2 = __ldg(gb + 2), gy2 = __ldg(gb + 3);
    float gw = gx2 - gx1 + 1.0f, gh = gy2 - gy1 + 1.0f;
    float gcx = gx1 + 0.5f * gw, gcy = gy1 + 0.5f * gh;

    float t2[4], t3[7];
    t2[0] = (gcx - cx) / w;
    t2[1] = (gcy - cy) / h;
    t2[2] = logf(gw / w);
    t2[3] = logf(gh / h);
    t3[0] = (__ldg(g3 + 0) - cx) / w;
    t3[1] = (__ldg(g3 + 1) - cy) / h;
    t3[2] = __ldg(g3 + 2) - __ldg(an + 4);
    t3[3] = logf(__ldg(g3 + 3) / __ldg(an + 5));
    t3[4] = logf(__ldg(g3 + 4) / __ldg(an + 6));
    t3[5] = logf(__ldg(g3 + 5) / __ldg(an + 7));
    t3[6] = __ldg(g3 + 6) - __ldg(an + 8);

    const float4 p2 = __ldg(reinterpret_cast<const float4*>(b2) + b * A_TOTAL + a);
    float p2a[4] = {p2.x, p2.y, p2.z, p2.w};
    l2 = 0.0f; l3 = 0.0f;
    #pragma unroll
    for (int i = 0; i < 4; ++i) {
        float tv = (t2[i] - __ldg(mn + i)) / __ldg(sd + i);
        l2 += smooth_l1(p2a[i] - tv);
    }
    const float* p3 = b3 + (size_t)(b * A_TOTAL + a) * 7;
    #pragma unroll
    for (int i = 0; i < 7; ++i) {
        float tv = (t3[i] - __ldg(mn + 4 + i)) / __ldg(sd + 4 + i);
        l3 += smooth_l1(__ldg(p3 + i) - tv);
    }
}

__device__ __forceinline__ float lse4(float4 c) {
    float m = fmaxf(fmaxf(c.x, c.y), fmaxf(c.z, c.w));
    float se = __expf(c.x - m) + __expf(c.y - m) + __expf(c.z - m) + __expf(c.w - m);
    return m + __logf(se);
}

__device__ __forceinline__ float sel4(float4 c, int lbl) {
    return (lbl == 0) ? c.x : (lbl == 1) ? c.y : (lbl == 2) ? c.z : c.w;
}

// ------------------------------- k_main ------------------------------------
__global__ __launch_bounds__(128) void k_main(
    const float* __restrict__ cls,       // [B,A,4]
    const float* __restrict__ b2,        // [B,A,4]
    const float* __restrict__ b3,        // [B,A,7]
    const float* __restrict__ gtb,       // [B,G,4]
    const float* __restrict__ gt3,       // [B,G,7]
    const int*   __restrict__ glbl,      // [B,G]
    const int*   __restrict__ gval,      // [B,G]
    const float* __restrict__ anc,       // [NA,9]
    const float* __restrict__ mn,        // [1,11]
    const float* __restrict__ sd)        // [1,11]
{
    __shared__ float4 s_g4[NG];          // {gx1, gx2+1, ag, ih_row0}
    __shared__ float  s_ih1[NG];         // ih_row1
    __shared__ int    s_gidx[NG];
    __shared__ int    s_cnt, s_any;
    __shared__ float  s_red[4][5];

    int b   = blockIdx.y;
    int na  = blockIdx.x % NA;
    int hp  = blockIdx.x / NA;           // row pair index
    int hr0 = hp * 2;
    int t   = threadIdx.x;

    const float* an = anc + na * 9;
    float ax1 = __ldg(an + 0), ay1 = __ldg(an + 1);
    float ax2 = __ldg(an + 2), ay2 = __ldg(an + 3);

    // per-row y geometry, computed exactly as R10 (row's own sy)
    float sy0 = hr0 * STRIDEF;
    float sy1 = (hr0 + 1) * STRIDEF;
    float y1_0 = sy0 + ay1, y2p_0 = sy0 + ay2 + 1.0f;
    float y1_1 = sy1 + ay1, y2p_1 = sy1 + ay2 + 1.0f;
    float hgt0 = y2p_0 - y1_0;
    float hgt1 = y2p_1 - y1_1;

    if (t < 32) {                        // warp 0: gt preprocessing + compaction
        const float* gb = gtb + (b * NG + t) * 4;
        float gx1 = gb[0], gy1 = gb[1], gx2 = gb[2], gy2 = gb[3];
        int v = (gval[b * NG + t] != 0);
        float ih0 = fmaxf(fminf(y2p_0, gy2 + 1.0f) - fmaxf(y1_0, gy1), 0.0f);
        float ih1 = fmaxf(fminf(y2p_1, gy2 + 1.0f) - fmaxf(y1_1, gy1), 0.0f);
        int act = v && ((ih0 > 0.0f) || (ih1 > 0.0f));
        unsigned mact = __ballot_sync(0xFFFFFFFFu, act);
        unsigned mval = __ballot_sync(0xFFFFFFFFu, v);
        if (act) {
            int pos = __popc(mact & ((1u << t) - 1u));
            s_g4[pos] = make_float4(gx1, gx2 + 1.0f,
                                    (gx2 - gx1 + 1.0f) * (gy2 - gy1 + 1.0f), ih0);
            s_ih1[pos] = ih1;
            s_gidx[pos] = t;
        }
        if (t == 0) { s_cnt = __popc(mact); s_any = (mval != 0u); }
    }
    __syncthreads();

    int  valid_t = (t < FEAT_W);
    int  cnt = s_cnt;
    int  a0 = (hr0 * FEAT_W + t) * NA + na;
    int  a1 = a0 + FEAT_W * NA;

    float sx  = t * STRIDEF;
    float x1  = sx + ax1, x2p = sx + ax2 + 1.0f;
    float ar0 = (x2p - x1) * hgt0;
    float ar1 = (x2p - x1) * hgt1;

    float bI0 = -1.0f, bU0 = 1.0f;  int bJ0 = 0;
    float bI1 = -1.0f, bU1 = 1.0f;  int bJ1 = 0;
    int em0 = 0, em1 = 0;
    int gbase = b * NG;

    #pragma unroll 4
    for (int j = 0; j < cnt; ++j) {
        float4 q = s_g4[j];
        float ih1 = s_ih1[j];
        float iw = fmaxf(fminf(x2p, q.y) - fmaxf(x1, q.x), 0.0f);  // row-indep
        float in0 = iw * q.w;
        float in1 = iw * ih1;
        float un0 = (ar0 + q.z) - in0;
        float un1 = (ar1 + q.z) - in1;
        if (in0 * bU0 > bI0 * un0) { bI0 = in0; bU0 = un0; bJ0 = j; }
        if (in1 * bU1 > bI1 * un1) { bI1 = in1; bU1 = un1; bJ1 = j; }
        if (valid_t && in0 >= 0.3489f * un0) {     // widened; exact test in k_fixup
            float iou = in0 / un0;
            unsigned long long pk =
                (((unsigned long long)__float_as_uint(iou)) << 32) |
                (unsigned long long)(0xFFFFFFFFu - (unsigned)a0);
            atomicMax(&g_best[gbase + s_gidx[j]], pk);
            em0 = 1;
        }
        if (valid_t && in1 >= 0.3489f * un1) {
            float iou = in1 / un1;
            unsigned long long pk =
                (((unsigned long long)__float_as_uint(iou)) << 32) |
                (unsigned long long)(0xFFFFFFFFu - (unsigned)a1);
            atomicMax(&g_best[gbase + s_gidx[j]], pk);
            em1 = 1;
        }
    }

    int fgA = 0, bgA = 0, fgB = 0, bgB = 0;
    float r_ce = 0.0f, r_l2 = 0.0f, r_l3 = 0.0f;
    if (valid_t) {
        int anyv = s_any;
        // row 0
        {
            float q = bI0 / bU0;                   // IEEE div, as reference
            fgA = (cnt > 0) && (q >= 0.5f);
            bgA = (!fgA) && anyv;
            int agt = (cnt > 0) ? s_gidx[bJ0] : 0;
            if (em0)
                g_assign_buf[b * A_TOTAL + a0] = agt | (fgA << 8) | (bgA << 9);
            if (fgA | bgA) {
                const float4 c = __ldg(reinterpret_cast<const float4*>(cls) + b * A_TOTAL + a0);
                int lbl = fgA ? __ldg(&glbl[gbase + agt]) : 0;
                r_ce += lse4(c) - sel4(c, lbl);
            }
            if (fgA) {
                float l2, l3;
                reg_loss(a0, agt, b, b2, b3, gtb, gt3, anc, mn, sd, l2, l3);
                r_l2 += l2; r_l3 += l3;
            }
        }
        // row 1
        {
            float q = bI1 / bU1;
            fgB = (cnt > 0) && (q >= 0.5f);
            bgB = (!fgB) && anyv;
            int agt = (cnt > 0) ? s_gidx[bJ1] : 0;
            if (em1)
                g_assign_buf[b * A_TOTAL + a1] = agt | (fgB << 8) | (bgB << 9);
            if (fgB | bgB) {
                const float4 c = __ldg(reinterpret_cast<const float4*>(cls) + b * A_TOTAL + a1);
                int lbl = fgB ? __ldg(&glbl[gbase + agt]) : 0;
                r_ce += lse4(c) - sel4(c, lbl);
            }
            if (fgB) {
                float l2, l3;
                reg_loss(a1, agt, b, b2, b3, gtb, gt3, anc, mn, sd, l2, l3);
                r_l2 += l2; r_l3 += l3;
            }
        }
    }

    // block reduce -> bucketed atomics
    unsigned baA = __ballot_sync(0xFFFFFFFFu, fgA | bgA);
    unsigned baB = __ballot_sync(0xFFFFFFFFu, fgB | bgB);
    unsigned bfA = __ballot_sync(0xFFFFFFFFu, fgA);
    unsigned bfB = __ballot_sync(0xFFFFFFFFu, fgB);
    #pragma unroll
    for (int off = 16; off; off >>= 1)
        r_ce += __shfl_down_sync(0xFFFFFFFFu, r_ce, off);
    if (bfA | bfB) {
        #pragma unroll
        for (int off = 16; off; off >>= 1) {
            r_l2 += __shfl_down_sync(0xFFFFFFFFu, r_l2, off);
            r_l3 += __shfl_down_sync(0xFFFFFFFFu, r_l3, off);
        }
    }
    int wid = t >> 5, lane = t & 31;
    if (lane == 0) {
        s_red[wid][0] = r_ce;
        s_red[wid][1] = (float)(__popc(baA) + __popc(baB));
        s_red[wid][2] = (float)(__popc(bfA) + __popc(bfB));
        s_red[wid][3] = r_l2;
        s_red[wid][4] = r_l3;
    }
    __syncthreads();
    if (t == 0) {
        float u0 = 0, u1 = 0, u2 = 0, u3 = 0, u4 = 0;
        #pragma unroll
        for (int wv = 0; wv < 4; ++wv) {
            u0 += s_red[wv][0]; u1 += s_red[wv][1]; u2 += s_red[wv][2];
            u3 += s_red[wv][3]; u4 += s_red[wv][4];
        }
        int bucket = (blockIdx.x + blockIdx.y * 8) & (NBUCKET - 1);
        atomicAdd(&g_acc2[0 * NBUCKET + bucket], (double)u0);
        atomicAdd(&g_acc2[1 * NBUCKET + bucket], (double)u1);
        atomicAdd(&g_acc2[2 * NBUCKET + bucket], (double)u2);
        if (u2 > 0.0f) {
            atomicAdd(&g_acc2[3 * NBUCKET + bucket], (double)u3);
            atomicAdd(&g_acc2[4 * NBUCKET + bucket], (double)u4);
        }
    }
}

// ------------------------------- k_fixup -----------------------------------
// One block per (image b, gt g). 256 blocks -> no single-CTA throttle.
__global__ __launch_bounds__(32) void k_fixup(
    const float* __restrict__ cls,
    const float* __restrict__ b2,
    const float* __restrict__ b3,
    const float* __restrict__ gtb,
    const float* __restrict__ gt3,
    const int*   __restrict__ glbl,
    const int*   __restrict__ gval,
    const float* __restrict__ anc,
    const float* __restrict__ mn,
    const float* __restrict__ sd)
{
    int blk = blockIdx.x;                // 0..255
    int b = blk >> 5, g = blk & 31;
    int l = threadIdx.x;                 // 32 lanes: lane l handles gt l of image b

    unsigned long long pk = g_best[b * NG + l];
    float iou = __uint_as_float((unsigned)(pk >> 32));
    unsigned ba = 0xFFFFFFFFu - (unsigned)(pk & 0xFFFFFFFFull);
    int forced = (gval[b * NG + l] != 0) && (iou >= 0.35f);

    unsigned my_ba   = __shfl_sync(0xFFFFFFFFu, ba, g);
    int      my_frc  = __shfl_sync(0xFFFFFFFFu, forced, g);
    // winner = forced and no higher g (same image) forces the same anchor
    unsigned same = __ballot_sync(0xFFFFFFFFu, forced && (ba == my_ba));
    int winner = my_frc && ((same >> (g + 1)) == 0u);
    if (!winner || l != 0) return;

    int aa = (int)my_ba;
    int pko   = g_assign_buf[b * A_TOTAL + aa];
    int fg_o  = (pko >> 8) & 1;
    int bg_o  = (pko >> 9) & 1;
    int agt_o = pko & 0xFF;

    const float4 c = __ldg(reinterpret_cast<const float4*>(cls) + b * A_TOTAL + aa);
    float lse = lse4(c);
    int lbl_n = __ldg(&glbl[b * NG + g]);
    int lbl_o = fg_o ? __ldg(&glbl[b * NG + agt_o]) : 0;
    float ce_n = lse - sel4(c, lbl_n);
    float ce_o = (fg_o | bg_o) ? (lse - sel4(c, lbl_o)) : 0.0f;
    double dc0 = (double)ce_n - (double)ce_o;
    double dc1 = (fg_o | bg_o) ? 0.0 : 1.0;
    double dc2 = fg_o ? 0.0 : 1.0;

    float l2n, l3n;
    reg_loss(aa, g, b, b2, b3, gtb, gt3, anc, mn, sd, l2n, l3n);
    double dc3 = l2n, dc4 = l3n;
    if (fg_o) {
        float l2o, l3o;
        reg_loss(aa, agt_o, b, b2, b3, gtb, gt3, anc, mn, sd, l2o, l3o);
        dc3 -= (double)l2o; dc4 -= (double)l3o;
    }

    int bucket = blk & (NBUCKET - 1);
    if (dc0 != 0.0) atomicAdd(&g_acc2[0 * NBUCKET + bucket], dc0);
    if (dc1 != 0.0) atomicAdd(&g_acc2[1 * NBUCKET + bucket], dc1);
    if (dc2 != 0.0) atomicAdd(&g_acc2[2 * NBUCKET + bucket], dc2);
    if (dc3 != 0.0) atomicAdd(&g_acc2[3 * NBUCKET + bucket], dc3);
    if (dc4 != 0.0) atomicAdd(&g_acc2[4 * NBUCKET + bucket], dc4);
}

// ------------------------------- k_final -----------------------------------
// grid=1 x 32 threads; body kept minimal (single-CTA issue throttle).
__global__ __launch_bounds__(32) void k_final(float* __restrict__ out) {
    int l = threadIdx.x;
    double v[5];
    #pragma unroll
    for (int i = 0; i < 5; ++i)
        v[i] = g_acc2[i * NBUCKET + l] + g_acc2[i * NBUCKET + 32 + l];
    #pragma unroll
    for (int i = 0; i < 5; ++i)
        #pragma unroll
        for (int off = 16; off; off >>= 1)
            v[i] += __shfl_down_sync(0xFFFFFFFFu, v[i], off);
    if (l == 0) {
        double nact = v[1] > 1.0 ? v[1] : 1.0;
        double nfg  = v[2] > 1.0 ? v[2] : 1.0;
        out[0] = (float)(v[0] / nact + v[3] / nfg + v[4] / nfg);
    }
    __syncwarp();
    // restore invariant: scratch zero at next kernel_launch entry
    #pragma unroll
    for (int k = l; k < NB * NG; k += 32) g_best[k] = 0ull;
    #pragma unroll
    for (int k = l; k < 5 * NBUCKET; k += 32) g_acc2[k] = 0.0;
}

extern "C" void kernel_launch(void* const* d_in, const int* in_sizes, int n_in,
                              void* d_out, int out_size) {
    const float* cls  = (const float*)d_in[0];
    const float* b2   = (const float*)d_in[1];
    const float* b3   = (const float*)d_in[2];
    const float* gtb  = (const float*)d_in[3];
    const float* gt3  = (const float*)d_in[4];
    const int*   glbl = (const int*)d_in[5];
    const int*   gval = (const int*)d_in[6];
    const float* anc  = (const float*)d_in[7];
    const float* mn   = (const float*)d_in[8];
    const float* sd   = (const float*)d_in[9];
    float* out = (float*)d_out;

    k_main<<<dim3(NA * NPAIR, NB), 128>>>(cls, b2, b3, gtb, gt3, glbl, gval, anc, mn, sd);
    k_fixup<<<NB * NG, 32>>>(cls, b2, b3, gtb, gt3, glbl, gval, anc, mn, sd);
    k_final<<<1, 32>>>(out);
}

// round 17
// speedup vs baseline: 1.0681x; 1.0681x over previous
#include <cuda_runtime.h>
#include <cuda_bf16.h>
#include <math.h>

// ---------------------------------------------------------------------------
// RPN 3D loss, GB300 (sm_103a) — round 17: R10 kernel + per-warp x-overlap
// GT filtering (halves inner-loop iterations; outcomes bit-identical).
//
//  k_main  : grid 9216 x 128thr. Warp 0 compacts valid+y-overlapping GTs
//            (exactly as R10); then EACH warp sub-compacts to GTs whose x-span
//            can intersect any of its 32 columns (exact same-fp-ops interval
//            test -> no false negatives). Dense loop over the warp list.
//  k_fixup : grid 256 x 32thr — winner by ballot, signed corrections
//            (bit-identical recomputation).
//  k_final : separate tiny grid=1 launch (fusing measured worse: single-CTA
//            issue throttle, ~x38).
//
// gt_valid (jnp bool) arrives as int32.
// ---------------------------------------------------------------------------

#define FEAT_H 32
#define FEAT_W 110
#define NA 36
#define NB 8
#define NG 32
#define A_TOTAL (FEAT_H * FEAT_W * NA)   // 126720
#define STRIDEF 16.0f
#define NBUCKET 64

__device__ unsigned long long g_best[NB * NG];   // (iou_bits<<32)|(~anchor)
__device__ int g_assign_buf[NB * A_TOTAL];       // agt | fg<<8 | bg<<9 (pre-force)
__device__ double g_acc2[5 * NBUCKET];           // ce, n_act, n_fg, l2, l3

__device__ __forceinline__ float smooth_l1(float x) {
    float ax = fabsf(x);
    return ax < 1.0f ? 0.5f * ax * ax : ax - 0.5f;
}

// Single shared implementation: fix-up corrections rely on bitwise-identical
// recomputation of k_main contributions.
__device__ __forceinline__ void reg_loss(
    int a, int agt, int b,
    const float* __restrict__ b2, const float* __restrict__ b3,
    const float* __restrict__ gtb, const float* __restrict__ gt3,
    const float* __restrict__ anc, const float* __restrict__ mn,
    const float* __restrict__ sd, float& l2, float& l3)
{
    int na = a % NA;
    int hw = a / NA;
    int wc = hw % FEAT_W;
    int hr = hw / FEAT_W;
    const float* an = anc + na * 9;
    float sx = wc * STRIDEF, sy = hr * STRIDEF;
    float x1 = sx + __ldg(an + 0), y1 = sy + __ldg(an + 1);
    float x2 = sx + __ldg(an + 2), y2 = sy + __ldg(an + 3);
    float w  = x2 - x1 + 1.0f, h = y2 - y1 + 1.0f;
    float cx = x1 + 0.5f * w,  cy = y1 + 0.5f * h;

    const float* gb = gtb + (b * NG + agt) * 4;
    const float* g3 = gt3 + (b * NG + agt) * 7;
    float gx1 = __ldg(gb + 0), gy1 = __ldg(gb + 1);
    float gx2 = __ldg(gb + 2), gy2 = __ldg(gb + 3);
    float gw = gx2 - gx1 + 1.0f, gh = gy2 - gy1 + 1.0f;
    float gcx = gx1 + 0.5f * gw, gcy = gy1 + 0.5f * gh;

    float t2[4], t3[7];
    t2[0] = (gcx - cx) / w;
    t2[1] = (gcy - cy) / h;
    t2[2] = logf(gw / w);
    t2[3] = logf(gh / h);
    t3[0] = (__ldg(g3 + 0) - cx) / w;
    t3[1] = (__ldg(g3 + 1) - cy) / h;
    t3[2] = __ldg(g3 + 2) - __ldg(an + 4);
    t3[3] = logf(__ldg(g3 + 3) / __ldg(an + 5));
    t3[4] = logf(__ldg(g3 + 4) / __ldg(an + 6));
    t3[5] = logf(__ldg(g3 + 5) / __ldg(an + 7));
    t3[6] = __ldg(g3 + 6) - __ldg(an + 8);

    const float4 p2 = __ldg(reinterpret_cast<const float4*>(b2) + b * A_TOTAL + a);
    float p2a[4] = {p2.x, p2.y, p2.z, p2.w};
    l2 = 0.0f; l3 = 0.0f;
    #pragma unroll
    for (int i = 0; i < 4; ++i) {
        float tv = (t2[i] - __ldg(mn + i)) / __ldg(sd + i);
        l2 += smooth_l1(p2a[i] - tv);
    }
    const float* p3 = b3 + (size_t)(b * A_TOTAL + a) * 7;
    #pragma unroll
    for (int i = 0; i < 7; ++i) {
        float tv = (t3[i] - __ldg(mn + 4 + i)) / __ldg(sd + 4 + i);
        l3 += smooth_l1(__ldg(p3 + i) - tv);
    }
}

__device__ __forceinline__ float lse4(float4 c) {
    float m = fmaxf(fmaxf(c.x, c.y), fmaxf(c.z, c.w));
    float se = __expf(c.x - m) + __expf(c.y - m) + __expf(c.z - m) + __expf(c.w - m);
    return m + __logf(se);
}

__device__ __forceinline__ float sel4(float4 c, int lbl) {
    return (lbl == 0) ? c.x : (lbl == 1) ? c.y : (lbl == 2) ? c.z : c.w;
}

// ------------------------------- k_main ------------------------------------
__global__ __launch_bounds__(128) void k_main(
    const float* __restrict__ cls,       // [B,A,4]
    const float* __restrict__ b2,        // [B,A,4]
    const float* __restrict__ b3,        // [B,A,7]
    const float* __restrict__ gtb,       // [B,G,4]
    const float* __restrict__ gt3,       // [B,G,7]
    const int*   __restrict__ glbl,      // [B,G]
    const int*   __restrict__ gval,      // [B,G]
    const float* __restrict__ anc,       // [NA,9]
    const float* __restrict__ mn,        // [1,11]
    const float* __restrict__ sd)        // [1,11]
{
    __shared__ float4 s_g4[NG];          // {gx1, gx2+1, ag, ih}
    __shared__ int    s_gidx[NG];
    __shared__ int    s_cnt, s_any;
    __shared__ float4 s_w4[4][NG];       // per-warp filtered lists
    __shared__ int    s_wg[4][NG];
    __shared__ float  s_red[4][5];

    int b  = blockIdx.y;
    int na = blockIdx.x % NA;
    int hr = blockIdx.x / NA;
    int t  = threadIdx.x;
    int wv = t >> 5, lane = t & 31;

    const float* an = anc + na * 9;
    float ax1 = __ldg(an + 0), ay1 = __ldg(an + 1);
    float ax2 = __ldg(an + 2), ay2 = __ldg(an + 3);
    float sy  = hr * STRIDEF;
    float y1  = sy + ay1, y2p = sy + ay2 + 1.0f;
    float hgt = y2p - y1;

    if (t < 32) {                        // warp 0: gt preprocessing + compaction
        const float* gb = gtb + (b * NG + t) * 4;
        float gx1 = gb[0], gy1 = gb[1], gx2 = gb[2], gy2 = gb[3];
        int v = (gval[b * NG + t] != 0);
        float ih = fminf(y2p, gy2 + 1.0f) - fmaxf(y1, gy1);
        ih = fmaxf(ih, 0.0f);
        int act = v && (ih > 0.0f);
        unsigned mact = __ballot_sync(0xFFFFFFFFu, act);
        unsigned mval = __ballot_sync(0xFFFFFFFFu, v);
        if (act) {
            int pos = __popc(mact & ((1u << t) - 1u));
            s_g4[pos] = make_float4(gx1, gx2 + 1.0f,
                                    (gx2 - gx1 + 1.0f) * (gy2 - gy1 + 1.0f), ih);
            s_gidx[pos] = t;
        }
        if (t == 0) { s_cnt = __popc(mact); s_any = (mval != 0u); }
    }
    __syncthreads();

    int cnt = s_cnt;

    // per-warp x-overlap sub-compaction. Warp wv owns columns
    // [32*wv, min(109, 32*wv+31)]. Same fp ops as lane arithmetic below ->
    // any lane with iw>0 implies (wx1 < gx2p) && (wx2p > gx1): no false negs.
    int cfirst = wv * 32;
    int clast  = min(FEAT_W - 1, wv * 32 + 31);
    float wx1  = cfirst * STRIDEF + ax1;          // smallest x1 in warp
    float wx2p = clast * STRIDEF + ax2 + 1.0f;    // largest x2p in warp
    {
        int ok = (lane < cnt);
        float4 q = ok ? s_g4[lane] : make_float4(0.f, 0.f, 0.f, 0.f);
        int hit = ok && (q.x < wx2p) && (q.y > wx1);
        unsigned mh = __ballot_sync(0xFFFFFFFFu, hit);
        if (hit) {
            int pos = __popc(mh & ((1u << lane) - 1u));
            s_w4[wv][pos] = q;
            s_wg[wv][pos] = s_gidx[lane];
        }
        cnt = __popc(mh);                // warp-local count (uniform in warp)
    }
    __syncwarp();

    int  valid_t = (t < FEAT_W);
    int  a = (hr * FEAT_W + t) * NA + na;

    float sx  = t * STRIDEF;
    float x1  = sx + ax1, x2p = sx + ax2 + 1.0f;
    float ar  = (x2p - x1) * hgt;

    float bestI = -1.0f, bestU = 1.0f;
    int bestJ = 0;
    int emitted = 0;
    int gbase = b * NG;
    const float4* wlist = s_w4[wv];

    #pragma unroll 4
    for (int j = 0; j < cnt; ++j) {
        float4 q = wlist[j];
        float iw = fmaxf(fminf(x2p, q.y) - fmaxf(x1, q.x), 0.0f);
        float inter = iw * q.w;
        float uni   = (ar + q.z) - inter;
        if (inter * bestU > bestI * uni) { bestI = inter; bestU = uni; bestJ = j; }
        if (valid_t && inter >= 0.3489f * uni) {   // widened; exact test in k_fixup
            float iou = inter / uni;
            unsigned long long pk =
                (((unsigned long long)__float_as_uint(iou)) << 32) |
                (unsigned long long)(0xFFFFFFFFu - (unsigned)a);
            atomicMax(&g_best[gbase + s_wg[wv][j]], pk);
            emitted = 1;
        }
    }

    int fg0 = 0, bgc = 0, agt = 0;
    float r_ce = 0.0f, r_l2 = 0.0f, r_l3 = 0.0f;
    if (valid_t) {
        float q = bestI / bestU;                   // IEEE div, as reference
        fg0 = (cnt > 0) && (q >= 0.5f);            // cnt=warp list; fg needs iou>=0.5>0
        bgc = (!fg0) && s_any;
        agt = (cnt > 0) ? s_wg[wv][bestJ] : 0;     // consumed only when fg0
        // only candidate-emitting anchors can be read by k_fixup
        if (emitted)
            g_assign_buf[b * A_TOTAL + a] = agt | (fg0 << 8) | (bgc << 9);

        if (fg0 | bgc) {
            const float4 c = __ldg(reinterpret_cast<const float4*>(cls) + b * A_TOTAL + a);
            int lbl = fg0 ? __ldg(&glbl[b * NG + agt]) : 0;
            r_ce = lse4(c) - sel4(c, lbl);
        }
        if (fg0)
            reg_loss(a, agt, b, b2, b3, gtb, gt3, anc, mn, sd, r_l2, r_l3);
    }

    // block reduce -> bucketed atomics
    unsigned ba_act = __ballot_sync(0xFFFFFFFFu, fg0 | bgc);
    unsigned ba_fg  = __ballot_sync(0xFFFFFFFFu, fg0);
    #pragma unroll
    for (int off = 16; off; off >>= 1)
        r_ce += __shfl_down_sync(0xFFFFFFFFu, r_ce, off);
    if (ba_fg) {
        #pragma unroll
        for (int off = 16; off; off >>= 1) {
            r_l2 += __shfl_down_sync(0xFFFFFFFFu, r_l2, off);
            r_l3 += __shfl_down_sync(0xFFFFFFFFu, r_l3, off);
        }
    }
    if (lane == 0) {
        s_red[wv][0] = r_ce;
        s_red[wv][1] = (float)__popc(ba_act);
        s_red[wv][2] = (float)__popc(ba_fg);
        s_red[wv][3] = r_l2;
        s_red[wv][4] = r_l3;
    }
    __syncthreads();
    if (t == 0) {
        float u0 = 0, u1 = 0, u2 = 0, u3 = 0, u4 = 0;
        #pragma unroll
        for (int w2 = 0; w2 < 4; ++w2) {
            u0 += s_red[w2][0]; u1 += s_red[w2][1]; u2 += s_red[w2][2];
            u3 += s_red[w2][3]; u4 += s_red[w2][4];
        }
        int bucket = (blockIdx.x + blockIdx.y * 8) & (NBUCKET - 1);
        atomicAdd(&g_acc2[0 * NBUCKET + bucket], (double)u0);
        atomicAdd(&g_acc2[1 * NBUCKET + bucket], (double)u1);
        atomicAdd(&g_acc2[2 * NBUCKET + bucket], (double)u2);
        if (u2 > 0.0f) {
            atomicAdd(&g_acc2[3 * NBUCKET + bucket], (double)u3);
            atomicAdd(&g_acc2[4 * NBUCKET + bucket], (double)u4);
        }
    }
}

// ------------------------------- k_fixup -----------------------------------
// One block per (image b, gt g). 256 blocks -> no single-CTA throttle.
__global__ __launch_bounds__(32) void k_fixup(
    const float* __restrict__ cls,
    const float* __restrict__ b2,
    const float* __restrict__ b3,
    const float* __restrict__ gtb,
    const float* __restrict__ gt3,
    const int*   __restrict__ glbl,
    const int*   __restrict__ gval,
    const float* __restrict__ anc,
    const float* __restrict__ mn,
    const float* __restrict__ sd)
{
    int blk = blockIdx.x;                // 0..255
    int b = blk >> 5, g = blk & 31;
    int l = threadIdx.x;                 // 32 lanes: lane l handles gt l of image b

    unsigned long long pk = g_best[b * NG + l];
    float iou = __uint_as_float((unsigned)(pk >> 32));
    unsigned ba = 0xFFFFFFFFu - (unsigned)(pk & 0xFFFFFFFFull);
    int forced = (gval[b * NG + l] != 0) && (iou >= 0.35f);

    unsigned my_ba   = __shfl_sync(0xFFFFFFFFu, ba, g);
    int      my_frc  = __shfl_sync(0xFFFFFFFFu, forced, g);
    // winner = forced and no higher g (same image) forces the same anchor
    unsigned same = __ballot_sync(0xFFFFFFFFu, forced && (ba == my_ba));
    int winner = my_frc && ((same >> (g + 1)) == 0u);
    if (!winner || l != 0) return;

    int aa = (int)my_ba;
    int pko   = g_assign_buf[b * A_TOTAL + aa];
    int fg_o  = (pko >> 8) & 1;
    int bg_o  = (pko >> 9) & 1;
    int agt_o = pko & 0xFF;

    const float4 c = __ldg(reinterpret_cast<const float4*>(cls) + b * A_TOTAL + aa);
    float lse = lse4(c);
    int lbl_n = __ldg(&glbl[b * NG + g]);
    int lbl_o = fg_o ? __ldg(&glbl[b * NG + agt_o]) : 0;
    float ce_n = lse - sel4(c, lbl_n);
    float ce_o = (fg_o | bg_o) ? (lse - sel4(c, lbl_o)) : 0.0f;
    double dc0 = (double)ce_n - (double)ce_o;
    double dc1 = (fg_o | bg_o) ? 0.0 : 1.0;
    double dc2 = fg_o ? 0.0 : 1.0;

    float l2n, l3n;
    reg_loss(aa, g, b, b2, b3, gtb, gt3, anc, mn, sd, l2n, l3n);
    double dc3 = l2n, dc4 = l3n;
    if (fg_o) {
        float l2o, l3o;
        reg_loss(aa, agt_o, b, b2, b3, gtb, gt3, anc, mn, sd, l2o, l3o);
        dc3 -= (double)l2o; dc4 -= (double)l3o;
    }

    int bucket = blk & (NBUCKET - 1);
    if (dc0 != 0.0) atomicAdd(&g_acc2[0 * NBUCKET + bucket], dc0);
    if (dc1 != 0.0) atomicAdd(&g_acc2[1 * NBUCKET + bucket], dc1);
    if (dc2 != 0.0) atomicAdd(&g_acc2[2 * NBUCKET + bucket], dc2);
    if (dc3 != 0.0) atomicAdd(&g_acc2[3 * NBUCKET + bucket], dc3);
    if (dc4 != 0.0) atomicAdd(&g_acc2[4 * NBUCKET + bucket], dc4);
}

// ------------------------------- k_final -----------------------------------
// grid=1 x 32 threads; body kept minimal (single-CTA issue throttle).
__global__ __launch_bounds__(32) void k_final(float* __restrict__ out) {
    int l = threadIdx.x;
    double v[5];
    #pragma unroll
    for (int i = 0; i < 5; ++i)
        v[i] = g_acc2[i * NBUCKET + l] + g_acc2[i * NBUCKET + 32 + l];
    #pragma unroll
    for (int i = 0; i < 5; ++i)
        #pragma unroll
        for (int off = 16; off; off >>= 1)
            v[i] += __shfl_down_sync(0xFFFFFFFFu, v[i], off);
    if (l == 0) {
        double nact = v[1] > 1.0 ? v[1] : 1.0;
        double nfg  = v[2] > 1.0 ? v[2] : 1.0;
        out[0] = (float)(v[0] / nact + v[3] / nfg + v[4] / nfg);
    }
    __syncwarp();
    // restore invariant: scratch zero at next kernel_launch entry
    #pragma unroll
    for (int k = l; k < NB * NG; k += 32) g_best[k] = 0ull;
    #pragma unroll
    for (int k = l; k < 5 * NBUCKET; k += 32) g_acc2[k] = 0.0;
}

extern "C" void kernel_launch(void* const* d_in, const int* in_sizes, int n_in,
                              void* d_out, int out_size) {
    const float* cls  = (const float*)d_in[0];
    const float* b2   = (const float*)d_in[1];
    const float* b3   = (const float*)d_in[2];
    const float* gtb  = (const float*)d_in[3];
    const float* gt3  = (const float*)d_in[4];
    const int*   glbl = (const int*)d_in[5];
    const int*   gval = (const int*)d_in[6];
    const float* anc  = (const float*)d_in[7];
    const float* mn   = (const float*)d_in[8];
    const float* sd   = (const float*)d_in[9];
    float* out = (float*)d_out;

    k_main<<<dim3(NA * FEAT_H, NB), 128>>>(cls, b2, b3, gtb, gt3, glbl, gval, anc, mn, sd);
    k_fixup<<<NB * NG, 32>>>(cls, b2, b3, gtb, gt3, glbl, gval, anc, mn, sd);
    k_final<<<1, 32>>>(out);
}